// round 2
// baseline (speedup 1.0000x reference)
#include <cuda_runtime.h>
#include <math.h>

// Problem constants
#define BB 2
#define TT 2048
#define CC 4096
#define NH 32
#define NG 8
#define HS 128
#define QKV_N 6144            // (32 + 2*8) * 128
#define ROWS 4096             // B*T

// Scratch (no cudaMalloc allowed)
__device__ float g_qkv[(size_t)ROWS * QKV_N];   // ~100 MB
__device__ float g_y[(size_t)ROWS * CC];        // ~64 MB

// ---------------------------------------------------------------------------
// SGEMM  C[M,N] = A[M,K] @ B[N,K]^T   (NT, all row-major)
// BM=BN=128, BK=16, 256 threads, 8x8 micro-tile
// ---------------------------------------------------------------------------
__global__ void __launch_bounds__(256) sgemm_nt_kernel(
    const float* __restrict__ A, const float* __restrict__ B,
    float* __restrict__ C, int M, int N, int K)
{
    const int BM = 128, BN = 128, BK = 16;
    __shared__ float As[BK][BM];
    __shared__ float Bs[BK][BN];

    const int tid = threadIdx.x;
    const int tx = tid & 15;          // n direction
    const int ty = tid >> 4;          // m direction
    const int bm = blockIdx.y * BM;
    const int bn = blockIdx.x * BN;

    const int lr = tid >> 2;          // 0..63
    const int lc = (tid & 3) << 2;    // 0,4,8,12

    const float* Ab = A + (size_t)bm * K;
    const float* Bb = B + (size_t)bn * K;

    float acc[8][8];
    #pragma unroll
    for (int i = 0; i < 8; i++)
        #pragma unroll
        for (int j = 0; j < 8; j++) acc[i][j] = 0.f;

    for (int k0 = 0; k0 < K; k0 += BK) {
        __syncthreads();
        #pragma unroll
        for (int rr = 0; rr < 2; rr++) {
            int r = lr + rr * 64;
            float4 av = *(const float4*)(Ab + (size_t)r * K + k0 + lc);
            As[lc + 0][r] = av.x; As[lc + 1][r] = av.y;
            As[lc + 2][r] = av.z; As[lc + 3][r] = av.w;
            float4 bv = *(const float4*)(Bb + (size_t)r * K + k0 + lc);
            Bs[lc + 0][r] = bv.x; Bs[lc + 1][r] = bv.y;
            Bs[lc + 2][r] = bv.z; Bs[lc + 3][r] = bv.w;
        }
        __syncthreads();

        #pragma unroll
        for (int kk = 0; kk < BK; kk++) {
            float a[8], b[8];
            *(float4*)(a)     = *(const float4*)&As[kk][ty * 8];
            *(float4*)(a + 4) = *(const float4*)&As[kk][ty * 8 + 4];
            *(float4*)(b)     = *(const float4*)&Bs[kk][tx * 8];
            *(float4*)(b + 4) = *(const float4*)&Bs[kk][tx * 8 + 4];
            #pragma unroll
            for (int i = 0; i < 8; i++)
                #pragma unroll
                for (int j = 0; j < 8; j++)
                    acc[i][j] += a[i] * b[j];
        }
    }

    #pragma unroll
    for (int i = 0; i < 8; i++) {
        size_t row = (size_t)(bm + ty * 8 + i) * N + bn + tx * 8;
        float4 v0 = make_float4(acc[i][0], acc[i][1], acc[i][2], acc[i][3]);
        float4 v1 = make_float4(acc[i][4], acc[i][5], acc[i][6], acc[i][7]);
        *(float4*)(C + row)     = v0;
        *(float4*)(C + row + 4) = v1;
    }
}

// ---------------------------------------------------------------------------
// RoPE applied in place to q heads (slots 0..3) and k head (slot 4) of each
// group. One thread handles one (row, rope-head, d<64) pair.
// total = ROWS*40*64 = 10,485,760 (exact multiple of 256 — no bounds check)
// ---------------------------------------------------------------------------
__global__ void rope_kernel(float* __restrict__ qkv,
                            const float* __restrict__ cosb,
                            const float* __restrict__ sinb)
{
    int idx = blockIdx.x * blockDim.x + threadIdx.x;
    int d   = idx & 63;
    int hl  = (idx >> 6) % 40;
    int row = idx / (40 * 64);
    int g = hl / 5, slot = hl % 5;
    float* p = qkv + (size_t)row * QKV_N + (g * 6 + slot) * HS;
    int t = row & (TT - 1);
    float c = cosb[t * HS + d];
    float s = sinb[t * HS + d];
    float x1 = p[d], x2 = p[d + 64];
    p[d]      = x1 * c - x2 * s;
    p[d + 64] = x2 * c + x1 * s;
}

// ---------------------------------------------------------------------------
// Flash attention (fp32, causal). 64x64 tiles, D=128, 256 threads.
// Reads Q/K/V directly from the (rope'd) qkv buffer; writes Y in [B,T,H,D].
// ---------------------------------------------------------------------------
#define QST 132    // padded row stride for Q/K/V tiles
#define SST 68     // padded row stride for score tile

__global__ void __launch_bounds__(256) flash_kernel(
    const float* __restrict__ qkv, float* __restrict__ Y)
{
    extern __shared__ float sm[];
    float* Qs = sm;                    // 64 * 132
    float* Ks = Qs + 64 * QST;
    float* Vs = Ks + 64 * QST;
    float* Ss = Vs + 64 * QST;         // 64 * 68
    float* mrow = Ss + 64 * SST;       // 64
    float* lrow = mrow + 64;           // 64
    float* arow = lrow + 64;           // 64

    const int tid = threadIdx.x;
    const int qs = blockIdx.x * 64;
    const int bh = blockIdx.y;
    const int b = bh >> 5, h = bh & 31;
    const int g = h >> 2, qslot = h & 3;
    const float* base = qkv + (size_t)b * TT * QKV_N;
    const int qcol = (g * 6 + qslot) * HS;
    const int kcol = (g * 6 + 4) * HS;
    const int vcol = (g * 6 + 5) * HS;

    // load Q tile: 64 rows x 128 cols
    for (int i = tid; i < 64 * 32; i += 256) {
        int r = i >> 5, c4 = (i & 31) << 2;
        *(float4*)&Qs[r * QST + c4] =
            *(const float4*)(base + (size_t)(qs + r) * QKV_N + qcol + c4);
    }
    if (tid < 64) { mrow[tid] = -3.0e38f; lrow[tid] = 0.f; }

    float acc[4][8];
    #pragma unroll
    for (int i = 0; i < 4; i++)
        #pragma unroll
        for (int j = 0; j < 8; j++) acc[i][j] = 0.f;

    const int ty = tid >> 4, tx = tid & 15;
    const int rm = ty * 4;             // row base (phase1 & phase3)
    const int cn = tx * 8;             // output col base (phase3)
    const float scale = 0.08838834764831845f;  // 1/sqrt(128)

    for (int ks = 0; ks <= qs; ks += 64) {
        __syncthreads();               // previous phase3 done with Ks/Vs/Ss
        for (int i = tid; i < 64 * 32; i += 256) {
            int r = i >> 5, c4 = (i & 31) << 2;
            *(float4*)&Ks[r * QST + c4] =
                *(const float4*)(base + (size_t)(ks + r) * QKV_N + kcol + c4);
            *(float4*)&Vs[r * QST + c4] =
                *(const float4*)(base + (size_t)(ks + r) * QKV_N + vcol + c4);
        }
        __syncthreads();

        // phase 1: S = scale * Q @ K^T (+ causal mask on diagonal tile)
        float s[4][4];
        #pragma unroll
        for (int i = 0; i < 4; i++)
            #pragma unroll
            for (int j = 0; j < 4; j++) s[i][j] = 0.f;
        for (int kk = 0; kk < HS; kk++) {
            float a[4], bb[4];
            #pragma unroll
            for (int i = 0; i < 4; i++) a[i] = Qs[(rm + i) * QST + kk];
            #pragma unroll
            for (int j = 0; j < 4; j++) bb[j] = Ks[(tx * 4 + j) * QST + kk];
            #pragma unroll
            for (int i = 0; i < 4; i++)
                #pragma unroll
                for (int j = 0; j < 4; j++) s[i][j] += a[i] * bb[j];
        }
        const bool diag = (ks == qs);
        #pragma unroll
        for (int i = 0; i < 4; i++)
            #pragma unroll
            for (int j = 0; j < 4; j++) {
                float v = s[i][j] * scale;
                if (diag && (tx * 4 + j) > (rm + i)) v = -3.0e38f;
                Ss[(rm + i) * SST + tx * 4 + j] = v;
            }
        __syncthreads();

        // phase 2: online softmax. 4 threads per row.
        {
            int row = tid >> 2, c0 = tid & 3;
            float tmax = -3.0e38f;
            for (int c = c0; c < 64; c += 4)
                tmax = fmaxf(tmax, Ss[row * SST + c]);
            tmax = fmaxf(tmax, __shfl_xor_sync(0xffffffffu, tmax, 1));
            tmax = fmaxf(tmax, __shfl_xor_sync(0xffffffffu, tmax, 2));
            float mold = mrow[row];
            float mnew = fmaxf(mold, tmax);
            float psum = 0.f;
            for (int c = c0; c < 64; c += 4) {
                float p = __expf(Ss[row * SST + c] - mnew);
                Ss[row * SST + c] = p;
                psum += p;
            }
            psum += __shfl_xor_sync(0xffffffffu, psum, 1);
            psum += __shfl_xor_sync(0xffffffffu, psum, 2);
            if (c0 == 0) {
                float alpha = __expf(mold - mnew);
                mrow[row] = mnew;
                lrow[row] = lrow[row] * alpha + psum;
                arow[row] = alpha;
            }
        }
        __syncthreads();

        // phase 3: acc = acc*alpha + P @ V
        float al[4];
        #pragma unroll
        for (int i = 0; i < 4; i++) al[i] = arow[rm + i];
        #pragma unroll
        for (int i = 0; i < 4; i++)
            #pragma unroll
            for (int j = 0; j < 8; j++) acc[i][j] *= al[i];
        for (int kk = 0; kk < 64; kk++) {
            float p[4];
            #pragma unroll
            for (int i = 0; i < 4; i++) p[i] = Ss[(rm + i) * SST + kk];
            float4 v0 = *(const float4*)&Vs[kk * QST + cn];
            float4 v1 = *(const float4*)&Vs[kk * QST + cn + 4];
            float vv[8] = {v0.x, v0.y, v0.z, v0.w, v1.x, v1.y, v1.z, v1.w};
            #pragma unroll
            for (int i = 0; i < 4; i++)
                #pragma unroll
                for (int j = 0; j < 8; j++) acc[i][j] += p[i] * vv[j];
        }
    }

    // epilogue: divide by l, write Y[b, t, h*128 + d]
    float inv[4];
    #pragma unroll
    for (int i = 0; i < 4; i++) inv[i] = 1.f / lrow[rm + i];
    #pragma unroll
    for (int i = 0; i < 4; i++) {
        size_t row = (size_t)(b * TT + qs + rm + i) * CC + h * HS + cn;
        float4 v0 = make_float4(acc[i][0] * inv[i], acc[i][1] * inv[i],
                                acc[i][2] * inv[i], acc[i][3] * inv[i]);
        float4 v1 = make_float4(acc[i][4] * inv[i], acc[i][5] * inv[i],
                                acc[i][6] * inv[i], acc[i][7] * inv[i]);
        *(float4*)(Y + row)     = v0;
        *(float4*)(Y + row + 4) = v1;
    }
}

// ---------------------------------------------------------------------------
extern "C" void kernel_launch(void* const* d_in, const int* in_sizes, int n_in,
                              void* d_out, int out_size)
{
    const float* x     = (const float*)d_in[0];
    const float* cosb  = (const float*)d_in[1];
    const float* sinb  = (const float*)d_in[2];
    const float* Wqkv  = (const float*)d_in[3];
    const float* Wproj = (const float*)d_in[4];
    float* out = (float*)d_out;

    float* qkv = nullptr;
    float* y   = nullptr;
    cudaGetSymbolAddress((void**)&qkv, g_qkv);
    cudaGetSymbolAddress((void**)&y, g_y);

    const int flash_smem = (3 * 64 * QST + 64 * SST + 3 * 64) * (int)sizeof(float);
    cudaFuncSetAttribute(flash_kernel,
                         cudaFuncAttributeMaxDynamicSharedMemorySize, flash_smem);

    // 1) qkv = x @ Wqkv^T      [4096, 6144]
    {
        dim3 grid(QKV_N / 128, ROWS / 128);
        sgemm_nt_kernel<<<grid, 256>>>(x, Wqkv, qkv, ROWS, QKV_N, CC);
    }
    // 2) RoPE in place on q/k heads
    {
        int total = ROWS * 40 * 64;
        rope_kernel<<<total / 256, 256>>>(qkv, cosb, sinb);
    }
    // 3) attention -> y [B,T,C]
    {
        dim3 grid(TT / 64, BB * NH);
        flash_kernel<<<grid, 256, flash_smem>>>(qkv, y);
    }
    // 4) out = y @ Wproj^T     [4096, 4096]
    {
        dim3 grid(CC / 128, ROWS / 128);
        sgemm_nt_kernel<<<grid, 256>>>(y, Wproj, out, ROWS, CC, CC);
    }
}

// round 14
// speedup vs baseline: 1.5911x; 1.5911x over previous
#include <cuda_runtime.h>
#include <cuda_bf16.h>
#include <stdint.h>
#include <math.h>

// Problem constants
#define BB 2
#define TT 2048
#define CC 4096
#define NH 32
#define NG 8
#define HS 128
#define QKV_N 6144            // (32 + 2*8) * 128
#define ROWS 4096             // B*T

// Scratch (no cudaMalloc allowed)
__device__ float g_qkv[(size_t)ROWS * QKV_N];   // ~100 MB
__device__ float g_y[(size_t)ROWS * CC];        // ~64 MB

__device__ __forceinline__ uint32_t smem_u32(const void* p) {
    uint32_t a;
    asm("{ .reg .u64 t; cvta.to.shared.u64 t, %1; cvt.u32.u64 %0, t; }"
        : "=r"(a) : "l"(p));
    return a;
}

// ldmatrix x4 (sm_75+, family-common)
__device__ __forceinline__ void ldmx4(uint32_t* r, uint32_t addr) {
    asm volatile("ldmatrix.sync.aligned.m8n8.x4.shared.b16 {%0,%1,%2,%3}, [%4];"
                 : "=r"(r[0]), "=r"(r[1]), "=r"(r[2]), "=r"(r[3]) : "r"(addr));
}

// mma.sync m16n8k16 bf16 -> fp32 (sm_80+, family-common)
__device__ __forceinline__ void mma16816(float* d, const uint32_t* a, const uint32_t* b) {
    asm volatile(
        "mma.sync.aligned.m16n8k16.row.col.f32.bf16.bf16.f32 "
        "{%0,%1,%2,%3}, {%4,%5,%6,%7}, {%8,%9}, {%0,%1,%2,%3};\n"
        : "+f"(d[0]), "+f"(d[1]), "+f"(d[2]), "+f"(d[3])
        : "r"(a[0]), "r"(a[1]), "r"(a[2]), "r"(a[3]), "r"(b[0]), "r"(b[1]));
}

__device__ __forceinline__ uint32_t pack_bf16(__nv_bfloat16 a, __nv_bfloat16 b) {
    __nv_bfloat162 t = __halves2bfloat162(a, b);
    return *(uint32_t*)&t;
}

// ===========================================================================
// Split-bf16 mma.sync GEMM:  C[M,N] = A[M,K] @ B[N,K]^T  (fp32 in/out)
// Tile 128x128, BK=32, 8 warps (2x4), each warp 64x32 via m16n8k16.
// A@B ~= Ah@Bh + Ah@Bl + Al@Bh  (split done at load time)
// ===========================================================================
#define SAST 40                        // SMEM row stride (bf16 elems): 32 + 8 pad
#define TILE_B (128 * SAST * 2)        // 10240 bytes per 128x32 bf16 tile
#define STAGE_B (4 * TILE_B)           // Ah, Al, Bh, Bl
#define GM_SMEM (2 * STAGE_B)          // 81920 bytes (double buffered)

__global__ void __launch_bounds__(256) gemm_mma_kernel(
    const float* __restrict__ A, const float* __restrict__ B,
    float* __restrict__ C, int M, int N, int K)
{
    extern __shared__ char sm[];
    const uint32_t sb = smem_u32(sm);
    const int tid = threadIdx.x;
    const int wid = tid >> 5, lid = tid & 31;
    const int wm = wid & 1, wn = wid >> 1;           // 2 x 4 warp grid
    const int bm = blockIdx.y * 128, bn = blockIdx.x * 128;
    const float* Ab = A + (size_t)bm * K;
    const float* Bb = B + (size_t)bn * K;

    float acc[4][4][4];
    #pragma unroll
    for (int i = 0; i < 4; i++)
        #pragma unroll
        for (int j = 0; j < 4; j++)
            #pragma unroll
            for (int k = 0; k < 4; k++) acc[i][j][k] = 0.f;

    float4 pa[4], pb[4];

    // ---- global load into registers (128x32 fp32 each for A and B) --------
    auto ldg = [&](int k0) {
        #pragma unroll
        for (int i = 0; i < 4; i++) {
            int idx = tid + i * 256;           // 0..1023
            int r = idx >> 3, c4 = idx & 7;    // row 0..127, float4 slot 0..7
            pa[i] = *(const float4*)(Ab + (size_t)r * K + k0 + c4 * 4);
            pb[i] = *(const float4*)(Bb + (size_t)r * K + k0 + c4 * 4);
        }
    };
    // ---- split + store to SMEM stage s ------------------------------------
    auto sts = [&](int s) {
        char* base = sm + s * STAGE_B;
        #pragma unroll
        for (int i = 0; i < 4; i++) {
            int idx = tid + i * 256;
            int r = idx >> 3, c4 = idx & 7;
            uint32_t off = (uint32_t)(r * SAST + c4 * 4) * 2;

            __nv_bfloat16 h0 = __float2bfloat16(pa[i].x), h1 = __float2bfloat16(pa[i].y);
            __nv_bfloat16 h2 = __float2bfloat16(pa[i].z), h3 = __float2bfloat16(pa[i].w);
            *(uint2*)(base + off) = make_uint2(pack_bf16(h0, h1), pack_bf16(h2, h3));
            *(uint2*)(base + TILE_B + off) = make_uint2(
                pack_bf16(__float2bfloat16(pa[i].x - __bfloat162float(h0)),
                          __float2bfloat16(pa[i].y - __bfloat162float(h1))),
                pack_bf16(__float2bfloat16(pa[i].z - __bfloat162float(h2)),
                          __float2bfloat16(pa[i].w - __bfloat162float(h3))));

            __nv_bfloat16 g0 = __float2bfloat16(pb[i].x), g1 = __float2bfloat16(pb[i].y);
            __nv_bfloat16 g2 = __float2bfloat16(pb[i].z), g3 = __float2bfloat16(pb[i].w);
            *(uint2*)(base + 2 * TILE_B + off) = make_uint2(pack_bf16(g0, g1), pack_bf16(g2, g3));
            *(uint2*)(base + 3 * TILE_B + off) = make_uint2(
                pack_bf16(__float2bfloat16(pb[i].x - __bfloat162float(g0)),
                          __float2bfloat16(pb[i].y - __bfloat162float(g1))),
                pack_bf16(__float2bfloat16(pb[i].z - __bfloat162float(g2)),
                          __float2bfloat16(pb[i].w - __bfloat162float(g3))));
        }
    };
    // ---- compute one BK=32 chunk from stage s ------------------------------
    auto compute = [&](int s) {
        const uint32_t Abase = sb + s * STAGE_B;
        const uint32_t Bbase = Abase + 2 * TILE_B;
        #pragma unroll
        for (int ks = 0; ks < 2; ks++) {
            uint32_t af[4][4], bh[4][2], bl[4][2];
            // B fragments: hi and lo, 4 n-tiles of 8
            #pragma unroll
            for (int np = 0; np < 2; np++) {
                uint32_t n = wn * 32 + np * 16 + ((lid >> 4) & 1) * 8 + (lid & 7);
                uint32_t col = ks * 16 + ((lid >> 3) & 1) * 8;
                uint32_t bd = Bbase + (n * SAST + col) * 2;
                uint32_t r[4];
                ldmx4(r, bd);
                bh[np * 2][0] = r[0]; bh[np * 2][1] = r[1];
                bh[np * 2 + 1][0] = r[2]; bh[np * 2 + 1][1] = r[3];
                ldmx4(r, bd + TILE_B);
                bl[np * 2][0] = r[0]; bl[np * 2][1] = r[1];
                bl[np * 2 + 1][0] = r[2]; bl[np * 2 + 1][1] = r[3];
            }
            // A hi fragments; products Ah*Bh and Ah*Bl
            #pragma unroll
            for (int mt = 0; mt < 4; mt++) {
                uint32_t row = wm * 64 + mt * 16 + (lid & 15);
                uint32_t col = ks * 16 + (lid >> 4) * 8;
                ldmx4(af[mt], Abase + (row * SAST + col) * 2);
            }
            #pragma unroll
            for (int mt = 0; mt < 4; mt++)
                #pragma unroll
                for (int nt = 0; nt < 4; nt++) mma16816(acc[mt][nt], af[mt], bh[nt]);
            #pragma unroll
            for (int mt = 0; mt < 4; mt++)
                #pragma unroll
                for (int nt = 0; nt < 4; nt++) mma16816(acc[mt][nt], af[mt], bl[nt]);
            // A lo fragments; product Al*Bh
            #pragma unroll
            for (int mt = 0; mt < 4; mt++) {
                uint32_t row = wm * 64 + mt * 16 + (lid & 15);
                uint32_t col = ks * 16 + (lid >> 4) * 8;
                ldmx4(af[mt], Abase + TILE_B + (row * SAST + col) * 2);
            }
            #pragma unroll
            for (int mt = 0; mt < 4; mt++)
                #pragma unroll
                for (int nt = 0; nt < 4; nt++) mma16816(acc[mt][nt], af[mt], bh[nt]);
        }
    };

    // ---- pipeline: LDG(c+1) -> compute(c) -> STS(c+1) -> sync --------------
    const int NC = K >> 5;
    ldg(0); sts(0);
    __syncthreads();
    for (int c = 0; c < NC; c++) {
        if (c + 1 < NC) ldg((c + 1) << 5);
        compute(c & 1);
        if (c + 1 < NC) sts((c + 1) & 1);
        __syncthreads();
    }

    // ---- epilogue ----------------------------------------------------------
    #pragma unroll
    for (int mt = 0; mt < 4; mt++)
        #pragma unroll
        for (int nt = 0; nt < 4; nt++) {
            int r0 = bm + wm * 64 + mt * 16 + (lid >> 2);
            int c0 = bn + wn * 32 + nt * 8 + (lid & 3) * 2;
            *(float2*)(C + (size_t)r0 * N + c0) = make_float2(acc[mt][nt][0], acc[mt][nt][1]);
            *(float2*)(C + (size_t)(r0 + 8) * N + c0) = make_float2(acc[mt][nt][2], acc[mt][nt][3]);
        }
}

// ---------------------------------------------------------------------------
// RoPE applied in place to q heads (slots 0..3) and k head (slot 4).
// total = ROWS*40*64 = 10,485,760 (multiple of 256)
// ---------------------------------------------------------------------------
__global__ void rope_kernel(float* __restrict__ qkv,
                            const float* __restrict__ cosb,
                            const float* __restrict__ sinb)
{
    int idx = blockIdx.x * blockDim.x + threadIdx.x;
    int d   = idx & 63;
    int hl  = (idx >> 6) % 40;
    int row = idx / (40 * 64);
    int g = hl / 5, slot = hl % 5;
    float* p = qkv + (size_t)row * QKV_N + (g * 6 + slot) * HS;
    int t = row & (TT - 1);
    float c = cosb[t * HS + d];
    float s = sinb[t * HS + d];
    float x1 = p[d], x2 = p[d + 64];
    p[d]      = x1 * c - x2 * s;
    p[d + 64] = x2 * c + x1 * s;
}

// ---------------------------------------------------------------------------
// Flash attention (fp32, causal). 64x64 tiles, D=128, 256 threads.
// ---------------------------------------------------------------------------
#define QST 132
#define SST 68

__global__ void __launch_bounds__(256) flash_kernel(
    const float* __restrict__ qkv, float* __restrict__ Y)
{
    extern __shared__ float smf[];
    float* Qs = smf;
    float* Ks = Qs + 64 * QST;
    float* Vs = Ks + 64 * QST;
    float* Ss = Vs + 64 * QST;
    float* mrow = Ss + 64 * SST;
    float* lrow = mrow + 64;
    float* arow = lrow + 64;

    const int tid = threadIdx.x;
    const int qs = blockIdx.x * 64;
    const int bh = blockIdx.y;
    const int b = bh >> 5, h = bh & 31;
    const int g = h >> 2, qslot = h & 3;
    const float* base = qkv + (size_t)b * TT * QKV_N;
    const int qcol = (g * 6 + qslot) * HS;
    const int kcol = (g * 6 + 4) * HS;
    const int vcol = (g * 6 + 5) * HS;

    for (int i = tid; i < 64 * 32; i += 256) {
        int r = i >> 5, c4 = (i & 31) << 2;
        *(float4*)&Qs[r * QST + c4] =
            *(const float4*)(base + (size_t)(qs + r) * QKV_N + qcol + c4);
    }
    if (tid < 64) { mrow[tid] = -3.0e38f; lrow[tid] = 0.f; }

    float acc[4][8];
    #pragma unroll
    for (int i = 0; i < 4; i++)
        #pragma unroll
        for (int j = 0; j < 8; j++) acc[i][j] = 0.f;

    const int ty = tid >> 4, tx = tid & 15;
    const int rm = ty * 4;
    const int cn = tx * 8;
    const float scale = 0.08838834764831845f;

    for (int ks = 0; ks <= qs; ks += 64) {
        __syncthreads();
        for (int i = tid; i < 64 * 32; i += 256) {
            int r = i >> 5, c4 = (i & 31) << 2;
            *(float4*)&Ks[r * QST + c4] =
                *(const float4*)(base + (size_t)(ks + r) * QKV_N + kcol + c4);
            *(float4*)&Vs[r * QST + c4] =
                *(const float4*)(base + (size_t)(ks + r) * QKV_N + vcol + c4);
        }
        __syncthreads();

        float s[4][4];
        #pragma unroll
        for (int i = 0; i < 4; i++)
            #pragma unroll
            for (int j = 0; j < 4; j++) s[i][j] = 0.f;
        for (int kk = 0; kk < HS; kk++) {
            float a[4], bb[4];
            #pragma unroll
            for (int i = 0; i < 4; i++) a[i] = Qs[(rm + i) * QST + kk];
            #pragma unroll
            for (int j = 0; j < 4; j++) bb[j] = Ks[(tx * 4 + j) * QST + kk];
            #pragma unroll
            for (int i = 0; i < 4; i++)
                #pragma unroll
                for (int j = 0; j < 4; j++) s[i][j] += a[i] * bb[j];
        }
        const bool diag = (ks == qs);
        #pragma unroll
        for (int i = 0; i < 4; i++)
            #pragma unroll
            for (int j = 0; j < 4; j++) {
                float v = s[i][j] * scale;
                if (diag && (tx * 4 + j) > (rm + i)) v = -3.0e38f;
                Ss[(rm + i) * SST + tx * 4 + j] = v;
            }
        __syncthreads();

        {
            int row = tid >> 2, c0 = tid & 3;
            float tmax = -3.0e38f;
            for (int c = c0; c < 64; c += 4)
                tmax = fmaxf(tmax, Ss[row * SST + c]);
            tmax = fmaxf(tmax, __shfl_xor_sync(0xffffffffu, tmax, 1));
            tmax = fmaxf(tmax, __shfl_xor_sync(0xffffffffu, tmax, 2));
            float mold = mrow[row];
            float mnew = fmaxf(mold, tmax);
            float psum = 0.f;
            for (int c = c0; c < 64; c += 4) {
                float p = __expf(Ss[row * SST + c] - mnew);
                Ss[row * SST + c] = p;
                psum += p;
            }
            psum += __shfl_xor_sync(0xffffffffu, psum, 1);
            psum += __shfl_xor_sync(0xffffffffu, psum, 2);
            if (c0 == 0) {
                float alpha = __expf(mold - mnew);
                mrow[row] = mnew;
                lrow[row] = lrow[row] * alpha + psum;
                arow[row] = alpha;
            }
        }
        __syncthreads();

        float al[4];
        #pragma unroll
        for (int i = 0; i < 4; i++) al[i] = arow[rm + i];
        #pragma unroll
        for (int i = 0; i < 4; i++)
            #pragma unroll
            for (int j = 0; j < 8; j++) acc[i][j] *= al[i];
        for (int kk = 0; kk < 64; kk++) {
            float p[4];
            #pragma unroll
            for (int i = 0; i < 4; i++) p[i] = Ss[(rm + i) * SST + kk];
            float4 v0 = *(const float4*)&Vs[kk * QST + cn];
            float4 v1 = *(const float4*)&Vs[kk * QST + cn + 4];
            float vv[8] = {v0.x, v0.y, v0.z, v0.w, v1.x, v1.y, v1.z, v1.w};
            #pragma unroll
            for (int i = 0; i < 4; i++)
                #pragma unroll
                for (int j = 0; j < 8; j++) acc[i][j] += p[i] * vv[j];
        }
    }

    float inv[4];
    #pragma unroll
    for (int i = 0; i < 4; i++) inv[i] = 1.f / lrow[rm + i];
    #pragma unroll
    for (int i = 0; i < 4; i++) {
        size_t row = (size_t)(b * TT + qs + rm + i) * CC + h * HS + cn;
        float4 v0 = make_float4(acc[i][0] * inv[i], acc[i][1] * inv[i],
                                acc[i][2] * inv[i], acc[i][3] * inv[i]);
        float4 v1 = make_float4(acc[i][4] * inv[i], acc[i][5] * inv[i],
                                acc[i][6] * inv[i], acc[i][7] * inv[i]);
        *(float4*)(Y + row)     = v0;
        *(float4*)(Y + row + 4) = v1;
    }
}

// ---------------------------------------------------------------------------
extern "C" void kernel_launch(void* const* d_in, const int* in_sizes, int n_in,
                              void* d_out, int out_size)
{
    const float* x     = (const float*)d_in[0];
    const float* cosb  = (const float*)d_in[1];
    const float* sinb  = (const float*)d_in[2];
    const float* Wqkv  = (const float*)d_in[3];
    const float* Wproj = (const float*)d_in[4];
    float* out = (float*)d_out;

    float* qkv = nullptr;
    float* y   = nullptr;
    cudaGetSymbolAddress((void**)&qkv, g_qkv);
    cudaGetSymbolAddress((void**)&y, g_y);

    const int flash_smem = (3 * 64 * QST + 64 * SST + 3 * 64) * (int)sizeof(float);
    cudaFuncSetAttribute(flash_kernel,
                         cudaFuncAttributeMaxDynamicSharedMemorySize, flash_smem);
    cudaFuncSetAttribute(gemm_mma_kernel,
                         cudaFuncAttributeMaxDynamicSharedMemorySize, GM_SMEM);

    // 1) qkv = x @ Wqkv^T      [4096, 6144]
    {
        dim3 grid(QKV_N / 128, ROWS / 128);
        gemm_mma_kernel<<<grid, 256, GM_SMEM>>>(x, Wqkv, qkv, ROWS, QKV_N, CC);
    }
    // 2) RoPE in place on q/k heads
    {
        int total = ROWS * 40 * 64;
        rope_kernel<<<total / 256, 256>>>(qkv, cosb, sinb);
    }
    // 3) attention -> y [B,T,C]
    {
        dim3 grid(TT / 64, BB * NH);
        flash_kernel<<<grid, 256, flash_smem>>>(qkv, y);
    }
    // 4) out = y @ Wproj^T     [4096, 4096]
    {
        dim3 grid(CC / 128, ROWS / 128);
        gemm_mma_kernel<<<grid, 256, GM_SMEM>>>(y, Wproj, out, ROWS, CC, CC);
    }
}

// round 15
// speedup vs baseline: 3.5766x; 2.2479x over previous
#include <cuda_runtime.h>
#include <cuda_bf16.h>
#include <cuda_fp16.h>
#include <stdint.h>
#include <math.h>

// Problem constants
#define BB 2
#define TT 2048
#define CC 4096
#define NH 32
#define NG 8
#define HS 128
#define QKV_N 6144            // (32 + 2*8) * 128
#define ROWS 4096             // B*T

// Scratch (no cudaMalloc allowed)
__device__ float g_qkv[(size_t)ROWS * QKV_N];   // ~100 MB
__device__ float g_y[(size_t)ROWS * CC];        // ~64 MB

__device__ __forceinline__ uint32_t smem_u32(const void* p) {
    uint32_t a;
    asm("{ .reg .u64 t; cvta.to.shared.u64 t, %1; cvt.u32.u64 %0, t; }"
        : "=r"(a) : "l"(p));
    return a;
}

// ldmatrix x4 (sm_75+, family-common)
__device__ __forceinline__ void ldmx4(uint32_t* r, uint32_t addr) {
    asm volatile("ldmatrix.sync.aligned.m8n8.x4.shared.b16 {%0,%1,%2,%3}, [%4];"
                 : "=r"(r[0]), "=r"(r[1]), "=r"(r[2]), "=r"(r[3]) : "r"(addr));
}

// mma.sync m16n8k16 bf16 -> fp32 (sm_80+, family-common)
__device__ __forceinline__ void mma16816(float* d, const uint32_t* a, const uint32_t* b) {
    asm volatile(
        "mma.sync.aligned.m16n8k16.row.col.f32.bf16.bf16.f32 "
        "{%0,%1,%2,%3}, {%4,%5,%6,%7}, {%8,%9}, {%0,%1,%2,%3};\n"
        : "+f"(d[0]), "+f"(d[1]), "+f"(d[2]), "+f"(d[3])
        : "r"(a[0]), "r"(a[1]), "r"(a[2]), "r"(a[3]), "r"(b[0]), "r"(b[1]));
}

// mma.sync m16n8k16 fp16 -> fp32 (sm_80+, family-common)
__device__ __forceinline__ void mma16816h(float* d, const uint32_t* a, const uint32_t* b) {
    asm volatile(
        "mma.sync.aligned.m16n8k16.row.col.f32.f16.f16.f32 "
        "{%0,%1,%2,%3}, {%4,%5,%6,%7}, {%8,%9}, {%0,%1,%2,%3};\n"
        : "+f"(d[0]), "+f"(d[1]), "+f"(d[2]), "+f"(d[3])
        : "r"(a[0]), "r"(a[1]), "r"(a[2]), "r"(a[3]), "r"(b[0]), "r"(b[1]));
}

__device__ __forceinline__ uint32_t pack_bf16(__nv_bfloat16 a, __nv_bfloat16 b) {
    __nv_bfloat162 t = __halves2bfloat162(a, b);
    return *(uint32_t*)&t;
}
__device__ __forceinline__ uint32_t pack_h2(float a, float b) {
    __half2 h = __floats2half2_rn(a, b);
    return *(uint32_t*)&h;
}

// ===========================================================================
// Split-bf16 mma.sync GEMM (UNCHANGED from R14 — validated):
// C[M,N] = A[M,K] @ B[N,K]^T, tile 128x128, BK=32, 8 warps.
// ===========================================================================
#define SAST 40
#define TILE_B (128 * SAST * 2)
#define STAGE_B (4 * TILE_B)
#define GM_SMEM (2 * STAGE_B)

__global__ void __launch_bounds__(256) gemm_mma_kernel(
    const float* __restrict__ A, const float* __restrict__ B,
    float* __restrict__ C, int M, int N, int K)
{
    extern __shared__ char sm[];
    const uint32_t sb = smem_u32(sm);
    const int tid = threadIdx.x;
    const int wid = tid >> 5, lid = tid & 31;
    const int wm = wid & 1, wn = wid >> 1;
    const int bm = blockIdx.y * 128, bn = blockIdx.x * 128;
    const float* Ab = A + (size_t)bm * K;
    const float* Bb = B + (size_t)bn * K;

    float acc[4][4][4];
    #pragma unroll
    for (int i = 0; i < 4; i++)
        #pragma unroll
        for (int j = 0; j < 4; j++)
            #pragma unroll
            for (int k = 0; k < 4; k++) acc[i][j][k] = 0.f;

    float4 pa[4], pb[4];

    auto ldg = [&](int k0) {
        #pragma unroll
        for (int i = 0; i < 4; i++) {
            int idx = tid + i * 256;
            int r = idx >> 3, c4 = idx & 7;
            pa[i] = *(const float4*)(Ab + (size_t)r * K + k0 + c4 * 4);
            pb[i] = *(const float4*)(Bb + (size_t)r * K + k0 + c4 * 4);
        }
    };
    auto sts = [&](int s) {
        char* base = sm + s * STAGE_B;
        #pragma unroll
        for (int i = 0; i < 4; i++) {
            int idx = tid + i * 256;
            int r = idx >> 3, c4 = idx & 7;
            uint32_t off = (uint32_t)(r * SAST + c4 * 4) * 2;

            __nv_bfloat16 h0 = __float2bfloat16(pa[i].x), h1 = __float2bfloat16(pa[i].y);
            __nv_bfloat16 h2 = __float2bfloat16(pa[i].z), h3 = __float2bfloat16(pa[i].w);
            *(uint2*)(base + off) = make_uint2(pack_bf16(h0, h1), pack_bf16(h2, h3));
            *(uint2*)(base + TILE_B + off) = make_uint2(
                pack_bf16(__float2bfloat16(pa[i].x - __bfloat162float(h0)),
                          __float2bfloat16(pa[i].y - __bfloat162float(h1))),
                pack_bf16(__float2bfloat16(pa[i].z - __bfloat162float(h2)),
                          __float2bfloat16(pa[i].w - __bfloat162float(h3))));

            __nv_bfloat16 g0 = __float2bfloat16(pb[i].x), g1 = __float2bfloat16(pb[i].y);
            __nv_bfloat16 g2 = __float2bfloat16(pb[i].z), g3 = __float2bfloat16(pb[i].w);
            *(uint2*)(base + 2 * TILE_B + off) = make_uint2(pack_bf16(g0, g1), pack_bf16(g2, g3));
            *(uint2*)(base + 3 * TILE_B + off) = make_uint2(
                pack_bf16(__float2bfloat16(pb[i].x - __bfloat162float(g0)),
                          __float2bfloat16(pb[i].y - __bfloat162float(g1))),
                pack_bf16(__float2bfloat16(pb[i].z - __bfloat162float(g2)),
                          __float2bfloat16(pb[i].w - __bfloat162float(g3))));
        }
    };
    auto compute = [&](int s) {
        const uint32_t Abase = sb + s * STAGE_B;
        const uint32_t Bbase = Abase + 2 * TILE_B;
        #pragma unroll
        for (int ks = 0; ks < 2; ks++) {
            uint32_t af[4][4], bh[4][2], bl[4][2];
            #pragma unroll
            for (int np = 0; np < 2; np++) {
                uint32_t n = wn * 32 + np * 16 + ((lid >> 4) & 1) * 8 + (lid & 7);
                uint32_t col = ks * 16 + ((lid >> 3) & 1) * 8;
                uint32_t bd = Bbase + (n * SAST + col) * 2;
                uint32_t r[4];
                ldmx4(r, bd);
                bh[np * 2][0] = r[0]; bh[np * 2][1] = r[1];
                bh[np * 2 + 1][0] = r[2]; bh[np * 2 + 1][1] = r[3];
                ldmx4(r, bd + TILE_B);
                bl[np * 2][0] = r[0]; bl[np * 2][1] = r[1];
                bl[np * 2 + 1][0] = r[2]; bl[np * 2 + 1][1] = r[3];
            }
            #pragma unroll
            for (int mt = 0; mt < 4; mt++) {
                uint32_t row = wm * 64 + mt * 16 + (lid & 15);
                uint32_t col = ks * 16 + (lid >> 4) * 8;
                ldmx4(af[mt], Abase + (row * SAST + col) * 2);
            }
            #pragma unroll
            for (int mt = 0; mt < 4; mt++)
                #pragma unroll
                for (int nt = 0; nt < 4; nt++) mma16816(acc[mt][nt], af[mt], bh[nt]);
            #pragma unroll
            for (int mt = 0; mt < 4; mt++)
                #pragma unroll
                for (int nt = 0; nt < 4; nt++) mma16816(acc[mt][nt], af[mt], bl[nt]);
            #pragma unroll
            for (int mt = 0; mt < 4; mt++) {
                uint32_t row = wm * 64 + mt * 16 + (lid & 15);
                uint32_t col = ks * 16 + (lid >> 4) * 8;
                ldmx4(af[mt], Abase + TILE_B + (row * SAST + col) * 2);
            }
            #pragma unroll
            for (int mt = 0; mt < 4; mt++)
                #pragma unroll
                for (int nt = 0; nt < 4; nt++) mma16816(acc[mt][nt], af[mt], bh[nt]);
        }
    };

    const int NC = K >> 5;
    ldg(0); sts(0);
    __syncthreads();
    for (int c = 0; c < NC; c++) {
        if (c + 1 < NC) ldg((c + 1) << 5);
        compute(c & 1);
        if (c + 1 < NC) sts((c + 1) & 1);
        __syncthreads();
    }

    #pragma unroll
    for (int mt = 0; mt < 4; mt++)
        #pragma unroll
        for (int nt = 0; nt < 4; nt++) {
            int r0 = bm + wm * 64 + mt * 16 + (lid >> 2);
            int c0 = bn + wn * 32 + nt * 8 + (lid & 3) * 2;
            *(float2*)(C + (size_t)r0 * N + c0) = make_float2(acc[mt][nt][0], acc[mt][nt][1]);
            *(float2*)(C + (size_t)(r0 + 8) * N + c0) = make_float2(acc[mt][nt][2], acc[mt][nt][3]);
        }
}

// ---------------------------------------------------------------------------
// RoPE (unchanged)
// ---------------------------------------------------------------------------
__global__ void rope_kernel(float* __restrict__ qkv,
                            const float* __restrict__ cosb,
                            const float* __restrict__ sinb)
{
    int idx = blockIdx.x * blockDim.x + threadIdx.x;
    int d   = idx & 63;
    int hl  = (idx >> 6) % 40;
    int row = idx / (40 * 64);
    int g = hl / 5, slot = hl % 5;
    float* p = qkv + (size_t)row * QKV_N + (g * 6 + slot) * HS;
    int t = row & (TT - 1);
    float c = cosb[t * HS + d];
    float s = sinb[t * HS + d];
    float x1 = p[d], x2 = p[d + 64];
    p[d]      = x1 * c - x2 * s;
    p[d + 64] = x2 * c + x1 * s;
}

// ===========================================================================
// Flash attention with fp16 mma.sync (QK^T and PV on tensor cores).
// 64x64 tiles, D=128, 256 threads (8 warps, 2x4 m-n grid).
// Softmax stays fp32 (proven code path from R2).
// ===========================================================================
#define FQST 136      // fp16 row stride for Q/K tiles  (272 B = 17*16B)
#define FVST 72       // fp16 row stride for VT and P   (144 B = 9*16B)
#define SST  68       // fp32 row stride for S

// SMEM byte offsets
#define FS_Q   0
#define FS_K   (FS_Q + 64 * FQST * 2)          // 17408
#define FS_VT  (FS_K + 64 * FQST * 2)          // 34816
#define FS_S   (FS_VT + 128 * FVST * 2)        // 53248
#define FS_P   (FS_S + 64 * SST * 4)           // 70656
#define FS_M   (FS_P + 64 * FVST * 2)          // 79872
#define FS_L   (FS_M + 256)
#define FS_A   (FS_L + 256)
#define FLASH_SMEM (FS_A + 256)                // 80640

__global__ void __launch_bounds__(256) flash_kernel(
    const float* __restrict__ qkv, float* __restrict__ Y)
{
    extern __shared__ char smc[];
    const uint32_t sb = smem_u32(smc);
    float* Ss   = (float*)(smc + FS_S);
    __half* Ps  = (__half*)(smc + FS_P);
    float* mrow = (float*)(smc + FS_M);
    float* lrow = (float*)(smc + FS_L);
    float* arow = (float*)(smc + FS_A);

    const int tid = threadIdx.x;
    const int wid = tid >> 5, lid = tid & 31;
    const int wm = wid & 1, wn = wid >> 1;     // 2 x 4 warp grid
    const int qs = blockIdx.x * 64;
    const int bh = blockIdx.y;
    const int b = bh >> 5, h = bh & 31;
    const int g = h >> 2, qslot = h & 3;
    const float* base = qkv + (size_t)b * TT * QKV_N;
    const int qcol = (g * 6 + qslot) * HS;
    const int kcol = (g * 6 + 4) * HS;
    const int vcol = (g * 6 + 5) * HS;
    const float scale = 0.08838834764831845f;  // 1/sqrt(128)

    // load Q tile: 64 x 128 fp32 -> fp16
    for (int i = tid; i < 64 * 32; i += 256) {
        int r = i >> 5, c4 = (i & 31) << 2;
        float4 q = *(const float4*)(base + (size_t)(qs + r) * QKV_N + qcol + c4);
        *(uint2*)(smc + FS_Q + (r * FQST + c4) * 2) =
            make_uint2(pack_h2(q.x, q.y), pack_h2(q.z, q.w));
    }
    if (tid < 64) { mrow[tid] = -3.0e38f; lrow[tid] = 0.f; }

    // O accumulator fragments: rows wm*32 + mt*16, cols wn*32 + nt*8
    float acc[2][4][4];
    #pragma unroll
    for (int i = 0; i < 2; i++)
        #pragma unroll
        for (int j = 0; j < 4; j++)
            #pragma unroll
            for (int k = 0; k < 4; k++) acc[i][j][k] = 0.f;

    for (int ks0 = 0; ks0 <= qs; ks0 += 64) {
        __syncthreads();   // prior iteration done with Ks/VT/Ps
        // load K (fp16) and V (fp16, transposed) tiles
        for (int i = tid; i < 64 * 32; i += 256) {
            int r = i >> 5, c4 = (i & 31) << 2;
            float4 kv = *(const float4*)(base + (size_t)(ks0 + r) * QKV_N + kcol + c4);
            *(uint2*)(smc + FS_K + (r * FQST + c4) * 2) =
                make_uint2(pack_h2(kv.x, kv.y), pack_h2(kv.z, kv.w));
            float4 vv = *(const float4*)(base + (size_t)(ks0 + r) * QKV_N + vcol + c4);
            __half* vt = (__half*)(smc + FS_VT);
            vt[(c4 + 0) * FVST + r] = __float2half_rn(vv.x);
            vt[(c4 + 1) * FVST + r] = __float2half_rn(vv.y);
            vt[(c4 + 2) * FVST + r] = __float2half_rn(vv.z);
            vt[(c4 + 3) * FVST + r] = __float2half_rn(vv.w);
        }
        __syncthreads();

        // ---- phase 1: S = scale * Q @ K^T  (fp16 mma) -----------------
        float sacc[2][2][4];
        #pragma unroll
        for (int i = 0; i < 2; i++)
            #pragma unroll
            for (int j = 0; j < 2; j++)
                #pragma unroll
                for (int k = 0; k < 4; k++) sacc[i][j][k] = 0.f;
        #pragma unroll
        for (int ks = 0; ks < 8; ks++) {
            uint32_t af[2][4], bt[2][2];
            #pragma unroll
            for (int mt = 0; mt < 2; mt++) {
                uint32_t row = wm * 32 + mt * 16 + (lid & 15);
                uint32_t col = ks * 16 + (lid >> 4) * 8;
                ldmx4(af[mt], sb + FS_Q + (row * FQST + col) * 2);
            }
            {
                uint32_t n = wn * 16 + ((lid >> 4) & 1) * 8 + (lid & 7);
                uint32_t col = ks * 16 + ((lid >> 3) & 1) * 8;
                uint32_t r[4];
                ldmx4(r, sb + FS_K + (n * FQST + col) * 2);
                bt[0][0] = r[0]; bt[0][1] = r[1];
                bt[1][0] = r[2]; bt[1][1] = r[3];
            }
            #pragma unroll
            for (int mt = 0; mt < 2; mt++)
                #pragma unroll
                for (int nt = 0; nt < 2; nt++) mma16816h(sacc[mt][nt], af[mt], bt[nt]);
        }
        // write S fragments to SMEM with scale + causal mask
        #pragma unroll
        for (int mt = 0; mt < 2; mt++)
            #pragma unroll
            for (int nt = 0; nt < 2; nt++) {
                int rl0 = wm * 32 + mt * 16 + (lid >> 2);
                int cl  = wn * 16 + nt * 8 + (lid & 3) * 2;
                float v0 = sacc[mt][nt][0] * scale, v1 = sacc[mt][nt][1] * scale;
                float v2 = sacc[mt][nt][2] * scale, v3 = sacc[mt][nt][3] * scale;
                if (ks0 + cl     > qs + rl0)     v0 = -3.0e38f;
                if (ks0 + cl + 1 > qs + rl0)     v1 = -3.0e38f;
                if (ks0 + cl     > qs + rl0 + 8) v2 = -3.0e38f;
                if (ks0 + cl + 1 > qs + rl0 + 8) v3 = -3.0e38f;
                *(float2*)&Ss[rl0 * SST + cl]       = make_float2(v0, v1);
                *(float2*)&Ss[(rl0 + 8) * SST + cl] = make_float2(v2, v3);
            }
        __syncthreads();

        // ---- phase 2: online softmax (fp32, proven); write P as fp16 --
        {
            int row = tid >> 2, c0 = tid & 3;
            float tmax = -3.0e38f;
            for (int c = c0; c < 64; c += 4)
                tmax = fmaxf(tmax, Ss[row * SST + c]);
            tmax = fmaxf(tmax, __shfl_xor_sync(0xffffffffu, tmax, 1));
            tmax = fmaxf(tmax, __shfl_xor_sync(0xffffffffu, tmax, 2));
            float mold = mrow[row];
            float mnew = fmaxf(mold, tmax);
            float psum = 0.f;
            for (int c = c0; c < 64; c += 4) {
                float p = __expf(Ss[row * SST + c] - mnew);
                Ps[row * FVST + c] = __float2half_rn(p);
                psum += p;
            }
            psum += __shfl_xor_sync(0xffffffffu, psum, 1);
            psum += __shfl_xor_sync(0xffffffffu, psum, 2);
            if (c0 == 0) {
                float alpha = __expf(mold - mnew);
                mrow[row] = mnew;
                lrow[row] = lrow[row] * alpha + psum;
                arow[row] = alpha;
            }
        }
        __syncthreads();

        // ---- phase 3: acc = acc*alpha + P @ V  (fp16 mma) -------------
        #pragma unroll
        for (int mt = 0; mt < 2; mt++) {
            float a0 = arow[wm * 32 + mt * 16 + (lid >> 2)];
            float a1 = arow[wm * 32 + mt * 16 + (lid >> 2) + 8];
            #pragma unroll
            for (int nt = 0; nt < 4; nt++) {
                acc[mt][nt][0] *= a0; acc[mt][nt][1] *= a0;
                acc[mt][nt][2] *= a1; acc[mt][nt][3] *= a1;
            }
        }
        #pragma unroll
        for (int ks = 0; ks < 4; ks++) {
            uint32_t ap[2][4], bv[4][2];
            #pragma unroll
            for (int mt = 0; mt < 2; mt++) {
                uint32_t row = wm * 32 + mt * 16 + (lid & 15);
                uint32_t col = ks * 16 + (lid >> 4) * 8;
                ldmx4(ap[mt], sb + FS_P + (row * FVST + col) * 2);
            }
            #pragma unroll
            for (int np = 0; np < 2; np++) {
                uint32_t n = wn * 32 + np * 16 + ((lid >> 4) & 1) * 8 + (lid & 7);
                uint32_t col = ks * 16 + ((lid >> 3) & 1) * 8;
                uint32_t r[4];
                ldmx4(r, sb + FS_VT + (n * FVST + col) * 2);
                bv[np * 2][0] = r[0]; bv[np * 2][1] = r[1];
                bv[np * 2 + 1][0] = r[2]; bv[np * 2 + 1][1] = r[3];
            }
            #pragma unroll
            for (int mt = 0; mt < 2; mt++)
                #pragma unroll
                for (int nt = 0; nt < 4; nt++) mma16816h(acc[mt][nt], ap[mt], bv[nt]);
        }
    }

    // epilogue: divide by l, write Y[b*TT+qs+row][h*128 + col]
    #pragma unroll
    for (int mt = 0; mt < 2; mt++) {
        int rl0 = wm * 32 + mt * 16 + (lid >> 2);
        float inv0 = 1.f / lrow[rl0];
        float inv1 = 1.f / lrow[rl0 + 8];
        #pragma unroll
        for (int nt = 0; nt < 4; nt++) {
            int cl = h * HS + wn * 32 + nt * 8 + (lid & 3) * 2;
            size_t r0 = (size_t)(b * TT + qs + rl0) * CC + cl;
            size_t r1 = (size_t)(b * TT + qs + rl0 + 8) * CC + cl;
            *(float2*)(Y + r0) = make_float2(acc[mt][nt][0] * inv0, acc[mt][nt][1] * inv0);
            *(float2*)(Y + r1) = make_float2(acc[mt][nt][2] * inv1, acc[mt][nt][3] * inv1);
        }
    }
}

// ---------------------------------------------------------------------------
extern "C" void kernel_launch(void* const* d_in, const int* in_sizes, int n_in,
                              void* d_out, int out_size)
{
    const float* x     = (const float*)d_in[0];
    const float* cosb  = (const float*)d_in[1];
    const float* sinb  = (const float*)d_in[2];
    const float* Wqkv  = (const float*)d_in[3];
    const float* Wproj = (const float*)d_in[4];
    float* out = (float*)d_out;

    float* qkv = nullptr;
    float* y   = nullptr;
    cudaGetSymbolAddress((void**)&qkv, g_qkv);
    cudaGetSymbolAddress((void**)&y, g_y);

    cudaFuncSetAttribute(flash_kernel,
                         cudaFuncAttributeMaxDynamicSharedMemorySize, FLASH_SMEM);
    cudaFuncSetAttribute(gemm_mma_kernel,
                         cudaFuncAttributeMaxDynamicSharedMemorySize, GM_SMEM);

    // 1) qkv = x @ Wqkv^T      [4096, 6144]
    {
        dim3 grid(QKV_N / 128, ROWS / 128);
        gemm_mma_kernel<<<grid, 256, GM_SMEM>>>(x, Wqkv, qkv, ROWS, QKV_N, CC);
    }
    // 2) RoPE in place on q/k heads
    {
        int total = ROWS * 40 * 64;
        rope_kernel<<<total / 256, 256>>>(qkv, cosb, sinb);
    }
    // 3) attention -> y [B,T,C]
    {
        dim3 grid(TT / 64, BB * NH);
        flash_kernel<<<grid, 256, FLASH_SMEM>>>(qkv, y);
    }
    // 4) out = y @ Wproj^T     [4096, 4096]
    {
        dim3 grid(CC / 128, ROWS / 128);
        gemm_mma_kernel<<<grid, 256, GM_SMEM>>>(y, Wproj, out, ROWS, CC, CC);
    }
}